// round 15
// baseline (speedup 1.0000x reference)
#include <cuda_runtime.h>
#include <math.h>
#include <stdint.h>

#define DIM       128
#define NSPECIAL  4
#define MAX_POS   8192
#define MAXV      10240
#define NCMAX     128
#define CHUNK     80
#define MH        132            // M smem row stride (floats), 528B 16B-aligned
#define XS2       132            // xs row stride in gemm kernel

// ---- static device scratch ----
__device__ __align__(16) float g_lang[MAX_POS * DIM];
__device__ __align__(16) float g_U   [MAX_POS * DIM];
__device__ __align__(16) float g_Mp  [NCMAX * DIM * DIM];
__device__ __align__(16) float g_c0p [NCMAX * DIM];
__device__ __align__(16) float g_M   [DIM * DIM];
__device__ __align__(16) float g_c0  [DIM];

// ===========================================================================
// Kernel 1: EmbeddingBag(sum) + tanh. TWO warps per position; n==26 path is
// fully unrolled with all loads issued up-front (MLP 12-14 per thread).
// CTA = 256 threads = 4 positions x 2 half-warps.
// ===========================================================================
__global__ __launch_bounds__(256)
void bag_kernel(const float* __restrict__ ngram_emb,
                const int*   __restrict__ ngram_ids,
                const int*   __restrict__ ngram_offsets,
                const int*   __restrict__ x,
                int n_pos, int n_ngram_total, int n_words)
{
    __shared__ float part[4][128];

    const int wp   = threadIdx.x >> 5;
    const int p    = wp >> 1;
    const int h    = wp & 1;
    const int lane = threadIdx.x & 31;
    const int gw   = blockIdx.x * 4 + p;

    float4 acc = make_float4(0.f, 0.f, 0.f, 0.f);
    bool live = false;

    if (gw < n_pos) {
        int t = x[gw];
        if (t >= NSPECIAL) {
            live = true;
            int v   = t - NSPECIAL;
            int off = ngram_offsets[v];
            int end = (v + 1 < n_words) ? ngram_offsets[v + 1] : n_ngram_total;
            if (end - off == 26) {
                // fully unrolled: h=0 -> indices 0..3,8..11,16..19,24,25 (14)
                //                 h=1 -> indices 4..7,12..15,20..23      (12)
                int idx[14];
                int n = h ? 12 : 14;
#pragma unroll
                for (int k = 0; k < 12; ++k) {
                    int j = (k >> 2) * 8 + (k & 3) + h * 4;   // quad pairs
                    idx[k] = ngram_ids[off + j];
                }
                if (h == 0) { idx[12] = ngram_ids[off + 24]; idx[13] = ngram_ids[off + 25]; }
                float4 r[14];
#pragma unroll
                for (int k = 0; k < 14; ++k)
                    if (k < n)
                        r[k] = *(const float4*)(ngram_emb + (size_t)idx[k] * DIM + lane * 4);
#pragma unroll
                for (int k = 0; k < 14; ++k)
                    if (k < n) {
                        acc.x += r[k].x; acc.y += r[k].y;
                        acc.z += r[k].z; acc.w += r[k].w;
                    }
            } else {
                int nq = (end - off) >> 2;
                for (int k = h; k < nq; k += 2) {
                    int j = off + (k << 2);
                    int i0 = ngram_ids[j],     i1 = ngram_ids[j + 1];
                    int i2 = ngram_ids[j + 2], i3 = ngram_ids[j + 3];
                    float4 v0 = *(const float4*)(ngram_emb + (size_t)i0 * DIM + lane * 4);
                    float4 v1 = *(const float4*)(ngram_emb + (size_t)i1 * DIM + lane * 4);
                    float4 v2 = *(const float4*)(ngram_emb + (size_t)i2 * DIM + lane * 4);
                    float4 v3 = *(const float4*)(ngram_emb + (size_t)i3 * DIM + lane * 4);
                    acc.x += (v0.x + v1.x) + (v2.x + v3.x);
                    acc.y += (v0.y + v1.y) + (v2.y + v3.y);
                    acc.z += (v0.z + v1.z) + (v2.z + v3.z);
                    acc.w += (v0.w + v1.w) + (v2.w + v3.w);
                }
                if (h == 0)
                    for (int j = off + (nq << 2); j < end; ++j) {
                        float4 v0 = *(const float4*)(ngram_emb + (size_t)ngram_ids[j] * DIM + lane * 4);
                        acc.x += v0.x; acc.y += v0.y; acc.z += v0.z; acc.w += v0.w;
                    }
            }
        }
    }

    if (h == 1)
        *(float4*)&part[p][lane * 4] = acc;
    __syncthreads();

    if (h == 0 && gw < n_pos) {
        float4 o = make_float4(0.f, 0.f, 0.f, 0.f);
        if (live) {
            float4 q = *(const float4*)&part[p][lane * 4];
            o.x = tanhf(acc.x + q.x);
            o.y = tanhf(acc.y + q.y);
            o.z = tanhf(acc.z + q.z);
            o.w = tanhf(acc.w + q.w);
        }
        *(float4*)(g_lang + (size_t)gw * DIM + lane * 4) = o;
    }
}

// ===========================================================================
// Kernel 2: per-chunk partials of M = L^T L and c0 = sum_l L_l
// ===========================================================================
__global__ __launch_bounds__(256)
void msum_kernel(const float* __restrict__ latent, int n_latent)
{
    __shared__ float Ls[16][132];

    const int tid = threadIdx.x;
    const int tx  = tid & 15, ty = tid >> 4;
    const int R   = ty * 8, C = tx * 8;
    const int l0  = blockIdx.x * CHUNK;

    float acc[8][8];
#pragma unroll
    for (int i = 0; i < 8; ++i)
#pragma unroll
        for (int j = 0; j < 8; ++j) acc[i][j] = 0.f;
    float c0acc = 0.f;

    for (int b = 0; b < CHUNK / 16; ++b) {
        __syncthreads();
        for (int k = tid; k < 16 * 32; k += 256) {
            int row = k >> 5, c4 = (k & 31) << 2;
            int gl = l0 + b * 16 + row;
            float4 v = make_float4(0.f, 0.f, 0.f, 0.f);
            if (gl < n_latent)
                v = *(const float4*)(latent + (size_t)gl * DIM + c4);
            *(float4*)&Ls[row][c4] = v;
        }
        __syncthreads();
#pragma unroll
        for (int l = 0; l < 16; ++l) {
            float4 a0 = *(const float4*)&Ls[l][R];
            float4 a1 = *(const float4*)&Ls[l][R + 4];
            float4 b0 = *(const float4*)&Ls[l][C];
            float4 b1 = *(const float4*)&Ls[l][C + 4];
            float a[8]  = {a0.x, a0.y, a0.z, a0.w, a1.x, a1.y, a1.z, a1.w};
            float bb[8] = {b0.x, b0.y, b0.z, b0.w, b1.x, b1.y, b1.z, b1.w};
#pragma unroll
            for (int i = 0; i < 8; ++i)
#pragma unroll
                for (int j = 0; j < 8; ++j)
                    acc[i][j] += a[i] * bb[j];
        }
        if (tid < 128) {
#pragma unroll
            for (int l = 0; l < 16; ++l) c0acc += Ls[l][tid];
        }
    }

    float* mp = g_Mp + (size_t)blockIdx.x * DIM * DIM;
#pragma unroll
    for (int i = 0; i < 8; ++i) {
        *(float4*)&mp[(R + i) * DIM + C]     = make_float4(acc[i][0], acc[i][1], acc[i][2], acc[i][3]);
        *(float4*)&mp[(R + i) * DIM + C + 4] = make_float4(acc[i][4], acc[i][5], acc[i][6], acc[i][7]);
    }
    if (tid < 128) g_c0p[blockIdx.x * DIM + tid] = c0acc;
}

// ===========================================================================
// Kernel 3: reduce partials -> g_M, g_c0
// ===========================================================================
__global__ void reduce_kernel(int nc)
{
    int i = blockIdx.x * 256 + threadIdx.x;
    float s = 0.f;
    for (int c = 0; c < nc; ++c) s += g_Mp[(size_t)c * DIM * DIM + i];
    g_M[i] = s;
    if (blockIdx.x == 0 && threadIdx.x < DIM) {
        float cs = 0.f;
        for (int c = 0; c < nc; ++c) cs += g_c0p[c * DIM + threadIdx.x];
        g_c0[threadIdx.x] = cs;
    }
}

// ===========================================================================
// Kernel 4: GEMM  U = X @ M  (M symmetric, so row/col major agnostic).
// grid = (tok_tiles, 2): CTA = 128 tokens x 64 dims. 128 threads,
// thread tile = 8 tok x 8 dim -> 16 LDS per 256 FMA.
// ===========================================================================
__global__ __launch_bounds__(128)
void gemm_kernel(int n_pos)
{
    extern __shared__ float gs[];
    float* Mh = gs;                       // 64 * MH
    float* xs = Mh + 64 * MH;             // 128 e * XS2 tok

    const int tid  = threadIdx.x;
    const int tgrp = tid & 15;            // 16 groups x 8 tokens
    const int dgrp = tid >> 4;            // 8 groups x 8 dims
    const int pos0 = blockIdx.x * 128;
    const int dh   = blockIdx.y * 64;     // dim half base

    // load M half [64 x 128]
    for (int k = tid; k < 64 * 32; k += 128) {
        int r = k >> 5, c4 = (k & 31) << 2;
        *(float4*)&Mh[r * MH + c4] = *(const float4*)&g_M[(dh + r) * DIM + c4];
    }
    // load lang transposed: xs[e][tok]
    for (int k = tid; k < 128 * 32; k += 128) {
        int tk = k & 127;
        int q4 = k >> 7;                  // 0..31
        int pos = pos0 + tk;
        float4 v = make_float4(0.f, 0.f, 0.f, 0.f);
        if (pos < n_pos)
            v = *(const float4*)(g_lang + (size_t)pos * DIM + q4 * 4);
        xs[(q4 * 4 + 0) * XS2 + tk] = v.x;
        xs[(q4 * 4 + 1) * XS2 + tk] = v.y;
        xs[(q4 * 4 + 2) * XS2 + tk] = v.z;
        xs[(q4 * 4 + 3) * XS2 + tk] = v.w;
    }
    __syncthreads();

    const int t0 = tgrp * 8;
    const int d0 = dgrp * 8;

    float acc[8][8];                      // [tok][dim]
#pragma unroll
    for (int t = 0; t < 8; ++t)
#pragma unroll
        for (int i = 0; i < 8; ++i) acc[t][i] = 0.f;

#pragma unroll 2
    for (int e0 = 0; e0 < DIM; e0 += 4) {
        float4 xa[4], xb[4];
#pragma unroll
        for (int k = 0; k < 4; ++k) {
            xa[k] = *(const float4*)&xs[(e0 + k) * XS2 + t0];
            xb[k] = *(const float4*)&xs[(e0 + k) * XS2 + t0 + 4];
        }
#pragma unroll
        for (int i = 0; i < 8; ++i) {
            float4 m = *(const float4*)&Mh[(d0 + i) * MH + e0];   // warp 2-addr
            acc[0][i] += m.x * xa[0].x + m.y * xa[1].x + m.z * xa[2].x + m.w * xa[3].x;
            acc[1][i] += m.x * xa[0].y + m.y * xa[1].y + m.z * xa[2].y + m.w * xa[3].y;
            acc[2][i] += m.x * xa[0].z + m.y * xa[1].z + m.z * xa[2].z + m.w * xa[3].z;
            acc[3][i] += m.x * xa[0].w + m.y * xa[1].w + m.z * xa[2].w + m.w * xa[3].w;
            acc[4][i] += m.x * xb[0].x + m.y * xb[1].x + m.z * xb[2].x + m.w * xb[3].x;
            acc[5][i] += m.x * xb[0].y + m.y * xb[1].y + m.z * xb[2].y + m.w * xb[3].y;
            acc[6][i] += m.x * xb[0].z + m.y * xb[1].z + m.z * xb[2].z + m.w * xb[3].z;
            acc[7][i] += m.x * xb[0].w + m.y * xb[1].w + m.z * xb[2].w + m.w * xb[3].w;
        }
    }

    // write U
#pragma unroll
    for (int t = 0; t < 8; ++t) {
        int pos = pos0 + t0 + t;
        if (pos >= n_pos) continue;
        float* dst = g_U + (size_t)pos * DIM + dh + d0;
        *(float4*)dst       = make_float4(acc[t][0], acc[t][1], acc[t][2], acc[t][3]);
        *(float4*)(dst + 4) = make_float4(acc[t][4], acc[t][5], acc[t][6], acc[t][7]);
    }
}

// ===========================================================================
// Kernel 5: epilogue — warp per token.
//   q = x.u, cx = c0.x, D = V + cx + q/2, corr = 1 + q/2V
//   out = x + (c0*corr + u)/D  (special rows overridden)
// ===========================================================================
__global__ __launch_bounds__(256)
void epi_kernel(const float* __restrict__ special,
                const int*   __restrict__ xid,
                float*       __restrict__ out,
                int n_pos, float Vf)
{
    const int wp   = threadIdx.x >> 5;
    const int lane = threadIdx.x & 31;
    const int pos  = blockIdx.x * 8 + wp;
    if (pos >= n_pos) return;

    const int d = lane * 4;
    int id = xid[pos];

    if (id < NSPECIAL) {
        *(float4*)(out + (size_t)pos * DIM + d) = *(const float4*)(special + id * DIM + d);
        return;
    }

    float4 u4 = *(const float4*)(g_U    + (size_t)pos * DIM + d);
    float4 x4 = *(const float4*)(g_lang + (size_t)pos * DIM + d);
    float4 c4 = *(const float4*)(g_c0 + d);

    float qp = x4.x * u4.x + x4.y * u4.y + x4.z * u4.z + x4.w * u4.w;
    float cp = x4.x * c4.x + x4.y * c4.y + x4.z * c4.z + x4.w * c4.w;
#pragma unroll
    for (int s = 16; s > 0; s >>= 1) {
        qp += __shfl_xor_sync(0xffffffffu, qp, s);
        cp += __shfl_xor_sync(0xffffffffu, cp, s);
    }
    float D    = Vf + cp + 0.5f * qp;
    float inv  = 1.0f / D;
    float corr = 1.0f + qp / (2.0f * Vf);

    float4 o;
    o.x = x4.x + (c4.x * corr + u4.x) * inv;
    o.y = x4.y + (c4.y * corr + u4.y) * inv;
    o.z = x4.z + (c4.z * corr + u4.z) * inv;
    o.w = x4.w + (c4.w * corr + u4.w) * inv;
    *(float4*)(out + (size_t)pos * DIM + d) = o;
}

// ===========================================================================
extern "C" void kernel_launch(void* const* d_in, const int* in_sizes, int n_in,
                              void* d_out, int out_size)
{
    const float* ngram_emb     = (const float*)d_in[0];
    const float* latent        = (const float*)d_in[1];
    const float* special       = (const float*)d_in[2];
    const int*   ngram_ids     = (const int*)  d_in[3];
    const int*   ngram_offsets = (const int*)  d_in[4];
    const int*   x             = (const int*)  d_in[5];

    int n_pos    = in_sizes[5];
    int n_words  = in_sizes[4];
    int n_ngtot  = in_sizes[3];
    int n_latent = in_sizes[1] / DIM;
    if (n_pos > MAX_POS) n_pos = MAX_POS;
    if (n_latent > MAXV) n_latent = MAXV;

    float* out = (float*)d_out;

    int nc = (n_latent + CHUNK - 1) / CHUNK;

    bag_kernel<<<(n_pos + 3) / 4, 256>>>(ngram_emb, ngram_ids, ngram_offsets, x,
                                         n_pos, n_ngtot, n_words);

    msum_kernel<<<nc, 256>>>(latent, n_latent);

    reduce_kernel<<<64, 256>>>(nc);

    const int gsm = (64 * MH + 128 * XS2) * (int)sizeof(float);   // ~101 KB
    cudaFuncSetAttribute(gemm_kernel,
                         cudaFuncAttributeMaxDynamicSharedMemorySize, gsm);
    dim3 gg((n_pos + 127) / 128, 2);
    gemm_kernel<<<gg, 128, gsm>>>(n_pos);

    epi_kernel<<<(n_pos + 7) / 8, 256>>>(special, x, out, n_pos, (float)n_latent);
}

// round 16
// speedup vs baseline: 1.1702x; 1.1702x over previous
#include <cuda_runtime.h>
#include <math.h>
#include <stdint.h>

#define DIM       128
#define NSPECIAL  4
#define MAX_POS   8192
#define MAXV      10240
#define NCMAX     128
#define CHUNK     80

// ---- static device scratch ----
__device__ __align__(16) float g_lang[MAX_POS * DIM];
__device__ __align__(16) float g_Mp  [NCMAX * DIM * DIM];
__device__ __align__(16) float g_c0p [NCMAX * DIM];
__device__ __align__(16) float g_M   [DIM * DIM];
__device__ __align__(16) float g_c0  [DIM];

// ===========================================================================
// Kernel 1: EmbeddingBag(sum) + tanh. TWO half-warps per position; n==26
// path fully unrolled with all loads issued up-front (high MLP).
// CTA = 256 threads = 4 positions x 2 halves.
// ===========================================================================
__global__ __launch_bounds__(256)
void bag_kernel(const float* __restrict__ ngram_emb,
                const int*   __restrict__ ngram_ids,
                const int*   __restrict__ ngram_offsets,
                const int*   __restrict__ x,
                int n_pos, int n_ngram_total, int n_words)
{
    __shared__ float part[4][128];

    const int wp   = threadIdx.x >> 5;
    const int p    = wp >> 1;
    const int h    = wp & 1;
    const int lane = threadIdx.x & 31;
    const int gw   = blockIdx.x * 4 + p;

    float4 acc = make_float4(0.f, 0.f, 0.f, 0.f);
    bool live = false;

    if (gw < n_pos) {
        int t = x[gw];
        if (t >= NSPECIAL) {
            live = true;
            int v   = t - NSPECIAL;
            int off = ngram_offsets[v];
            int end = (v + 1 < n_words) ? ngram_offsets[v + 1] : n_ngram_total;
            if (end - off == 26) {
                int idx[14];
                int n = h ? 12 : 14;
#pragma unroll
                for (int k = 0; k < 12; ++k) {
                    int j = (k >> 2) * 8 + (k & 3) + h * 4;
                    idx[k] = ngram_ids[off + j];
                }
                if (h == 0) { idx[12] = ngram_ids[off + 24]; idx[13] = ngram_ids[off + 25]; }
                float4 r[14];
#pragma unroll
                for (int k = 0; k < 14; ++k)
                    if (k < n)
                        r[k] = *(const float4*)(ngram_emb + (size_t)idx[k] * DIM + lane * 4);
#pragma unroll
                for (int k = 0; k < 14; ++k)
                    if (k < n) {
                        acc.x += r[k].x; acc.y += r[k].y;
                        acc.z += r[k].z; acc.w += r[k].w;
                    }
            } else {
                int nq = (end - off) >> 2;
                for (int k = h; k < nq; k += 2) {
                    int j = off + (k << 2);
                    int i0 = ngram_ids[j],     i1 = ngram_ids[j + 1];
                    int i2 = ngram_ids[j + 2], i3 = ngram_ids[j + 3];
                    float4 v0 = *(const float4*)(ngram_emb + (size_t)i0 * DIM + lane * 4);
                    float4 v1 = *(const float4*)(ngram_emb + (size_t)i1 * DIM + lane * 4);
                    float4 v2 = *(const float4*)(ngram_emb + (size_t)i2 * DIM + lane * 4);
                    float4 v3 = *(const float4*)(ngram_emb + (size_t)i3 * DIM + lane * 4);
                    acc.x += (v0.x + v1.x) + (v2.x + v3.x);
                    acc.y += (v0.y + v1.y) + (v2.y + v3.y);
                    acc.z += (v0.z + v1.z) + (v2.z + v3.z);
                    acc.w += (v0.w + v1.w) + (v2.w + v3.w);
                }
                if (h == 0)
                    for (int j = off + (nq << 2); j < end; ++j) {
                        float4 v0 = *(const float4*)(ngram_emb + (size_t)ngram_ids[j] * DIM + lane * 4);
                        acc.x += v0.x; acc.y += v0.y; acc.z += v0.z; acc.w += v0.w;
                    }
            }
        }
    }

    if (h == 1)
        *(float4*)&part[p][lane * 4] = acc;
    __syncthreads();

    if (h == 0 && gw < n_pos) {
        float4 o = make_float4(0.f, 0.f, 0.f, 0.f);
        if (live) {
            float4 q = *(const float4*)&part[p][lane * 4];
            o.x = tanhf(acc.x + q.x);
            o.y = tanhf(acc.y + q.y);
            o.z = tanhf(acc.z + q.z);
            o.w = tanhf(acc.w + q.w);
        }
        *(float4*)(g_lang + (size_t)gw * DIM + lane * 4) = o;
    }
}

// ===========================================================================
// Kernel 2: per-chunk partials of M = L^T L and c0 = sum_l L_l
// ===========================================================================
__global__ __launch_bounds__(256)
void msum_kernel(const float* __restrict__ latent, int n_latent)
{
    __shared__ float Ls[16][132];

    const int tid = threadIdx.x;
    const int tx  = tid & 15, ty = tid >> 4;
    const int R   = ty * 8, C = tx * 8;
    const int l0  = blockIdx.x * CHUNK;

    float acc[8][8];
#pragma unroll
    for (int i = 0; i < 8; ++i)
#pragma unroll
        for (int j = 0; j < 8; ++j) acc[i][j] = 0.f;
    float c0acc = 0.f;

    for (int b = 0; b < CHUNK / 16; ++b) {
        __syncthreads();
        for (int k = tid; k < 16 * 32; k += 256) {
            int row = k >> 5, c4 = (k & 31) << 2;
            int gl = l0 + b * 16 + row;
            float4 v = make_float4(0.f, 0.f, 0.f, 0.f);
            if (gl < n_latent)
                v = *(const float4*)(latent + (size_t)gl * DIM + c4);
            *(float4*)&Ls[row][c4] = v;
        }
        __syncthreads();
#pragma unroll
        for (int l = 0; l < 16; ++l) {
            float4 a0 = *(const float4*)&Ls[l][R];
            float4 a1 = *(const float4*)&Ls[l][R + 4];
            float4 b0 = *(const float4*)&Ls[l][C];
            float4 b1 = *(const float4*)&Ls[l][C + 4];
            float a[8]  = {a0.x, a0.y, a0.z, a0.w, a1.x, a1.y, a1.z, a1.w};
            float bb[8] = {b0.x, b0.y, b0.z, b0.w, b1.x, b1.y, b1.z, b1.w};
#pragma unroll
            for (int i = 0; i < 8; ++i)
#pragma unroll
                for (int j = 0; j < 8; ++j)
                    acc[i][j] += a[i] * bb[j];
        }
        if (tid < 128) {
#pragma unroll
            for (int l = 0; l < 16; ++l) c0acc += Ls[l][tid];
        }
    }

    float* mp = g_Mp + (size_t)blockIdx.x * DIM * DIM;
#pragma unroll
    for (int i = 0; i < 8; ++i) {
        *(float4*)&mp[(R + i) * DIM + C]     = make_float4(acc[i][0], acc[i][1], acc[i][2], acc[i][3]);
        *(float4*)&mp[(R + i) * DIM + C + 4] = make_float4(acc[i][4], acc[i][5], acc[i][6], acc[i][7]);
    }
    if (tid < 128) g_c0p[blockIdx.x * DIM + tid] = c0acc;
}

// ===========================================================================
// Kernel 3: reduce partials -> g_M, g_c0
// ===========================================================================
__global__ void reduce_kernel(int nc)
{
    int i = blockIdx.x * 256 + threadIdx.x;
    float s = 0.f;
    for (int c = 0; c < nc; ++c) s += g_Mp[(size_t)c * DIM * DIM + i];
    g_M[i] = s;
    if (blockIdx.x == 0 && threadIdx.x < DIM) {
        float cs = 0.f;
        for (int c = 0; c < nc; ++c) cs += g_c0p[c * DIM + threadIdx.x];
        g_c0[threadIdx.x] = cs;
    }
}

// ===========================================================================
// Kernel 4 (fused mat-vec + epilogue): warp handles TWO tokens, lane owns
// dims 4*lane..4*lane+3. M read via coalesced LDG.128 (L1-resident, shared
// by both tokens); x[k] broadcast by register shuffle. No smem, no syncs.
//   u = M x;  q = x.u;  cx = c0.x;  D = V + cx + q/2;  corr = 1 + q/2V
//   out = x + (c0*corr + u)/D   (special rows overridden)
// ===========================================================================
__global__ __launch_bounds__(256)
void fused_final(const float* __restrict__ special,
                 const int*   __restrict__ xid,
                 float*       __restrict__ out,
                 int n_pos, float Vf)
{
    const int wp   = threadIdx.x >> 5;
    const int lane = threadIdx.x & 31;
    const int pa   = (blockIdx.x * 8 + wp) * 2;      // first token
    const int pb   = pa + 1;
    if (pa >= n_pos) return;

    const bool okb = (pb < n_pos);
    const int d = lane * 4;

    float4 xa = *(const float4*)(g_lang + (size_t)pa * DIM + d);
    float4 xb = okb ? *(const float4*)(g_lang + (size_t)pb * DIM + d)
                    : make_float4(0.f, 0.f, 0.f, 0.f);

    float4 ua = make_float4(0.f, 0.f, 0.f, 0.f);
    float4 ub = make_float4(0.f, 0.f, 0.f, 0.f);

    const float4* M4 = (const float4*)g_M;

#pragma unroll 8
    for (int g = 0; g < 32; ++g) {
#pragma unroll
        for (int k = 0; k < 4; ++k) {
            float sa = (k == 0) ? xa.x : (k == 1) ? xa.y : (k == 2) ? xa.z : xa.w;
            float sb = (k == 0) ? xb.x : (k == 1) ? xb.y : (k == 2) ? xb.z : xb.w;
            float va = __shfl_sync(0xffffffffu, sa, g);
            float vb = __shfl_sync(0xffffffffu, sb, g);
            float4 m = __ldg(&M4[(g * 4 + k) * 32 + lane]);   // M row, coalesced
            ua.x += va * m.x; ua.y += va * m.y; ua.z += va * m.z; ua.w += va * m.w;
            ub.x += vb * m.x; ub.y += vb * m.y; ub.z += vb * m.z; ub.w += vb * m.w;
        }
    }

    float4 c4 = __ldg((const float4*)(g_c0 + d));

    // q = x.u, cx = c0.x  (lane's u dims == lane's x dims)
    float qa = xa.x * ua.x + xa.y * ua.y + xa.z * ua.z + xa.w * ua.w;
    float qb = xb.x * ub.x + xb.y * ub.y + xb.z * ub.z + xb.w * ub.w;
    float ca = xa.x * c4.x + xa.y * c4.y + xa.z * c4.z + xa.w * c4.w;
    float cb = xb.x * c4.x + xb.y * c4.y + xb.z * c4.z + xb.w * c4.w;
#pragma unroll
    for (int s = 16; s > 0; s >>= 1) {
        qa += __shfl_xor_sync(0xffffffffu, qa, s);
        qb += __shfl_xor_sync(0xffffffffu, qb, s);
        ca += __shfl_xor_sync(0xffffffffu, ca, s);
        cb += __shfl_xor_sync(0xffffffffu, cb, s);
    }

    // token A
    {
        int id = xid[pa];
        float4 o;
        if (id < NSPECIAL) {
            o = *(const float4*)(special + id * DIM + d);
        } else {
            float D    = Vf + ca + 0.5f * qa;
            float inv  = 1.0f / D;
            float corr = 1.0f + qa / (2.0f * Vf);
            o.x = xa.x + (c4.x * corr + ua.x) * inv;
            o.y = xa.y + (c4.y * corr + ua.y) * inv;
            o.z = xa.z + (c4.z * corr + ua.z) * inv;
            o.w = xa.w + (c4.w * corr + ua.w) * inv;
        }
        *(float4*)(out + (size_t)pa * DIM + d) = o;
    }
    // token B
    if (okb) {
        int id = xid[pb];
        float4 o;
        if (id < NSPECIAL) {
            o = *(const float4*)(special + id * DIM + d);
        } else {
            float D    = Vf + cb + 0.5f * qb;
            float inv  = 1.0f / D;
            float corr = 1.0f + qb / (2.0f * Vf);
            o.x = xb.x + (c4.x * corr + ub.x) * inv;
            o.y = xb.y + (c4.y * corr + ub.y) * inv;
            o.z = xb.z + (c4.z * corr + ub.z) * inv;
            o.w = xb.w + (c4.w * corr + ub.w) * inv;
        }
        *(float4*)(out + (size_t)pb * DIM + d) = o;
    }
}

// ===========================================================================
extern "C" void kernel_launch(void* const* d_in, const int* in_sizes, int n_in,
                              void* d_out, int out_size)
{
    const float* ngram_emb     = (const float*)d_in[0];
    const float* latent        = (const float*)d_in[1];
    const float* special       = (const float*)d_in[2];
    const int*   ngram_ids     = (const int*)  d_in[3];
    const int*   ngram_offsets = (const int*)  d_in[4];
    const int*   x             = (const int*)  d_in[5];

    int n_pos    = in_sizes[5];
    int n_words  = in_sizes[4];
    int n_ngtot  = in_sizes[3];
    int n_latent = in_sizes[1] / DIM;
    if (n_pos > MAX_POS) n_pos = MAX_POS;
    if (n_latent > MAXV) n_latent = MAXV;

    float* out = (float*)d_out;

    int nc = (n_latent + CHUNK - 1) / CHUNK;

    bag_kernel<<<(n_pos + 3) / 4, 256>>>(ngram_emb, ngram_ids, ngram_offsets, x,
                                         n_pos, n_ngtot, n_words);

    msum_kernel<<<nc, 256>>>(latent, n_latent);

    reduce_kernel<<<64, 256>>>(nc);

    // 16 tokens per CTA (8 warps x 2 tokens)
    fused_final<<<(n_pos + 15) / 16, 256>>>(special, x, out, n_pos, (float)n_latent);
}